// round 10
// baseline (speedup 1.0000x reference)
#include <cuda_runtime.h>
#include <cuda_bf16.h>
#include <cstdint>
#include <math.h>

#define BB 16384
#define DD 4096
#define HH 128

// ---------------- scratch ----------------
__device__ __nv_bfloat16 g_xb[(size_t)BB * DD];     // visible sample (in-place chain)
__device__ __nv_bfloat16 g_Wx[2][(size_t)DD * HH];  // W splits, [d][h] (x-phase B)
__device__ __nv_bfloat16 g_Wh[2][(size_t)DD * HH];  // W splits, [h][d] (h-phase B)
__device__ double g_acc[4];

// ---------------- threefry2x32 (JAX-exact, verified R1-R9) ----------------
__host__ __device__ __forceinline__ uint32_t rotl32(uint32_t v, int s) {
  return (v << s) | (v >> (32 - s));
}
__host__ __device__ __forceinline__ void tf2x32(uint32_t k0, uint32_t k1,
                                                uint32_t x0, uint32_t x1,
                                                uint32_t &o0, uint32_t &o1) {
  uint32_t ks2 = k0 ^ k1 ^ 0x1BD11BDAu;
  x0 += k0; x1 += k1;
#define TF_R(r) { x0 += x1; x1 = rotl32(x1, r); x1 ^= x0; }
  TF_R(13) TF_R(15) TF_R(26) TF_R(6)   x0 += k1;  x1 += ks2 + 1u;
  TF_R(17) TF_R(29) TF_R(16) TF_R(24)  x0 += ks2; x1 += k0 + 2u;
  TF_R(13) TF_R(15) TF_R(26) TF_R(6)   x0 += k0;  x1 += k1 + 3u;
  TF_R(17) TF_R(29) TF_R(16) TF_R(24)  x0 += k1;  x1 += ks2 + 4u;
  TF_R(13) TF_R(15) TF_R(26) TF_R(6)   x0 += ks2; x1 += k0 + 5u;
#undef TF_R
  o0 = x0; o1 = x1;
}
__device__ __forceinline__ float jax_uniform01(uint32_t k0, uint32_t k1, uint32_t idx) {
  uint32_t a, b;
  tf2x32(k0, k1, 0u, idx, a, b);
  uint32_t bits = a ^ b;
  return __uint_as_float((bits >> 9) | 0x3F800000u) - 1.0f;
}
__device__ __forceinline__ float fast_sigmoid(float x) {
  float e, r;
  asm("ex2.approx.f32 %0, %1;" : "=f"(e) : "f"(-1.4426950408889634f * x));
  asm("rcp.approx.f32 %0, %1;" : "=f"(r) : "f"(1.0f + e));
  return r;
}
__device__ __forceinline__ float softplusf_(float x) {
  return fmaxf(x, 0.0f) + log1pf(expf(-fabsf(x)));
}

// ---------------- PTX helpers (baseline sm_100-safe) ----------------
__device__ __forceinline__ uint32_t smem_u32(const void *p) {
  uint32_t a;
  asm("{ .reg .u64 t; cvta.to.shared.u64 t, %1; cvt.u32.u64 %0, t; }"
      : "=r"(a) : "l"(p));
  return a;
}
__device__ __forceinline__ void ldsm4(uint32_t *r, uint32_t a) {
  asm volatile("ldmatrix.sync.aligned.m8n8.x4.shared.b16 {%0,%1,%2,%3}, [%4];"
               : "=r"(r[0]), "=r"(r[1]), "=r"(r[2]), "=r"(r[3]) : "r"(a));
}
__device__ __forceinline__ void mma_bf16(float *c, const uint32_t *a,
                                         uint32_t b0, uint32_t b1) {
  asm volatile(
      "mma.sync.aligned.m16n8k16.row.col.f32.bf16.bf16.f32 "
      "{%0,%1,%2,%3}, {%4,%5,%6,%7}, {%8,%9}, {%0,%1,%2,%3};"
      : "+f"(c[0]), "+f"(c[1]), "+f"(c[2]), "+f"(c[3])
      : "r"(a[0]), "r"(a[1]), "r"(a[2]), "r"(a[3]), "r"(b0), "r"(b1));
}
__device__ __forceinline__ uint32_t sw128(uint32_t o) {
  return o ^ ((o >> 3) & 0x70);
}
#define NB_SYNC(id, n) \
  asm volatile("bar.sync %0, %1;" :: "r"((uint32_t)(id)), "r"((uint32_t)(n)) : "memory")
#define NB_ARRIVE(id, n) \
  asm volatile("bar.arrive %0, %1;" :: "r"((uint32_t)(id)), "r"((uint32_t)(n)) : "memory")

// ---------------- smem layout (per CTA, 2 CTAs/SM) ----------------
// [0, 16384)      h buffer: 2 k-chunks x [64 rows x 128B] (SW128)
// [16384, 81920)  h-phase B pipe: 2 stages x (2 splits x 16KB)
// [16384, 49152)  x-phase B pipe: 2 stages x (2 splits x 8KB)   (union)
// [49152, 82944)  x-phase lin ping-pong: 2 x (64 rows x 264B fp32) (union)
// [83968, 100352) h-phase A pipe: 2 x 8KB
static constexpr int SM_H = 0;
static constexpr int SM_BH = 16384;
static constexpr int SM_BX = 16384;
static constexpr int SM_LIN = 49152;
static constexpr int LIN_BUF = 16896;  // 64 * 264
static constexpr int SM_A = 83968;
static constexpr int SMEM_BYTES = 100352;

// load [ROWS x 64 bf16] tile, 128B rows, SW128-swizzled, via cp.async
template <int LD, int ROWS, int THREADS>
__device__ __forceinline__ void load_tile(uint32_t sdst, const __nv_bfloat16 *g,
                                          int row0, int kt, int tid) {
#pragma unroll
  for (int i = 0; i < ROWS * 8 / THREADS; i++) {
    int idx = tid + THREADS * i;
    int r = idx >> 3, c = idx & 7;
    uint32_t sw = sw128((uint32_t)(r * 128 + c * 16));
    const void *ga = (const void *)(g + (size_t)(row0 + r) * LD + kt + c * 8);
    asm volatile("cp.async.cg.shared.global [%0], [%1], 16;"
                 :: "r"(sdst + sw), "l"(ga));
  }
}

// =============================================================
// Fused CD-4. Each CTA owns 64 batch rows.
// h-phase: all 8 warps GEMM (M64 N128 K4096, 2 splits).
// x-phase: warps 0-1 produce lin tiles (each M32 N64 K128, 2 splits),
//          warps 2-7 consume (threefry sample + bf16 gmem store).
// Barriers: waiter bar.sync, signaler bar.arrive.
//   full[s]=2+s:  64 P-arrive + 192 C-sync
//   empty[s]=4+s: 192 C-arrive (primed once) + 64 P-sync
//   id 1 (64):    producer-internal B-stage rendezvous
// =============================================================
__global__ void __launch_bounds__(256, 2)
fused_cd_kernel(const float *__restrict__ bx_, const float *__restrict__ bh_) {
  extern __shared__ char smem[];
  const uint32_t sb = smem_u32(smem);
  const int t = threadIdx.x, wid = t >> 5, l = t & 31;
  const int m0 = blockIdx.x * 64;
  const int q = l >> 2, tq = l & 3;
  const int wm = wid & 1;            // h-phase M-half; producer M-half (wid 0/1)
  const int wn = wid >> 1;           // h-phase N quarter (0..3)

  // ldmatrix.x4 per-lane base byte offsets
  uint32_t offA[2], offBh[2], offBp[4];
#pragma unroll
  for (int i = 0; i < 2; i++)
    offA[i] = (uint32_t)((wm * 32 + i * 16 + (l & 15)) * 128 + ((l >> 4) & 1) * 16);
#pragma unroll
  for (int jb = 0; jb < 2; jb++)
    offBh[jb] = (uint32_t)((wn * 32 + jb * 16 + (l & 7) + ((l >> 4) & 1) * 8) * 128 +
                           ((l >> 3) & 1) * 16);
#pragma unroll
  for (int jb = 0; jb < 4; jb++)
    offBp[jb] = (uint32_t)((jb * 16 + (l & 7) + ((l >> 4) & 1) * 8) * 128 +
                           ((l >> 3) & 1) * 16);

  float2 bias2h[4];
#pragma unroll
  for (int j = 0; j < 4; j++)
    bias2h[j] = *(const float2 *)&bh_[wn * 32 + j * 8 + 2 * tq];

  double sp0 = 0.0, sp1 = 0.0, spb = 0.0;
  const __nv_bfloat16 onev = __float2bfloat16(1.0f);
  const __nv_bfloat16 zerov = __float2bfloat16(0.0f);

  float acc[2][4][4];  // h-phase accumulators (32 regs)
  auto zacc = [&] {
#pragma unroll
    for (int i = 0; i < 2; i++)
#pragma unroll
      for (int j = 0; j < 4; j++)
#pragma unroll
        for (int v = 0; v < 4; v++) acc[i][j][v] = 0.0f;
  };

  auto issue_h = [&](int c) {  // all 256 threads
    int s = c & 1, kt = c * 64;
    load_tile<DD, 64, 256>(sb + SM_A + s * 8192, g_xb, m0, kt, t);
    load_tile<DD, 128, 256>(sb + SM_BH + s * 32768, g_Wh[0], 0, kt, t);
    load_tile<DD, 128, 256>(sb + SM_BH + s * 32768 + 16384, g_Wh[1], 0, kt, t);
    asm volatile("cp.async.commit_group;" ::: "memory");
  };
  auto issue_bx = [&](int g) {  // producers only (64 threads)
    int s = g & 1, n0 = (g >> 1) * 64, kt = (g & 1) * 64;
    load_tile<HH, 64, 64>(sb + SM_BX + s * 16384, g_Wx[0], n0, kt, t);
    load_tile<HH, 64, 64>(sb + SM_BX + s * 16384 + 8192, g_Wx[1], n0, kt, t);
    asm volatile("cp.async.commit_group;" ::: "memory");
  };
  auto do_chunk_h = [&](uint32_t abase, uint32_t bbase) {
#pragma unroll
    for (int kk = 0; kk < 4; kk++) {
      uint32_t a[2][4];
#pragma unroll
      for (int i = 0; i < 2; i++)
        ldsm4(a[i], abase + sw128(offA[i] + kk * 32));
#pragma unroll
      for (int p = 0; p < 2; p++) {
        uint32_t bb = bbase + 16384u * p;
#pragma unroll
        for (int jb = 0; jb < 2; jb++) {
          uint32_t b[4];
          ldsm4(b, bb + sw128(offBh[jb] + kk * 32));
#pragma unroll
          for (int i = 0; i < 2; i++) {
            mma_bf16(acc[i][jb * 2 + 0], a[i], b[0], b[1]);
            mma_bf16(acc[i][jb * 2 + 1], a[i], b[2], b[3]);
          }
        }
      }
    }
  };

  issue_h(0); issue_h(1);

#pragma unroll 1
  for (int step = 0; step <= 4; step++) {
    uint32_t hk0, hk1, xk0, xk1;
    tf2x32(0u, 42u, 0u, (uint32_t)(2 * step), hk0, hk1);
    tf2x32(0u, 42u, 0u, (uint32_t)(2 * step + 1), xk0, xk1);

    // ---------------- h phase: M64 N128 K4096, all 8 warps ----------------
    zacc();
#pragma unroll 1
    for (int c = 0; c < 64; c++) {
      if (c + 1 < 64) asm volatile("cp.async.wait_group 1;" ::: "memory");
      else            asm volatile("cp.async.wait_group 0;" ::: "memory");
      __syncthreads();
      do_chunk_h(sb + SM_A + (uint32_t)(c & 1) * 8192,
                 sb + SM_BH + (uint32_t)(c & 1) * 32768);
      __syncthreads();
      if (c + 2 < 64) issue_h(c + 2);
    }

    // h epilogue: softplus and/or sample into smem h buffer
#pragma unroll
    for (int i = 0; i < 2; i++) {
#pragma unroll
      for (int j = 0; j < 4; j++) {
        int c_loc = wn * 32 + j * 8 + 2 * tq;
#pragma unroll
        for (int h = 0; h < 2; h++) {
          int row = wm * 32 + i * 16 + q + h * 8;
          float l0 = acc[i][j][2 * h + 0] + bias2h[j].x;
          float l1 = acc[i][j][2 * h + 1] + bias2h[j].y;
          if (step == 0) sp0 += (double)softplusf_(l0) + (double)softplusf_(l1);
          if (step == 4) sp1 += (double)softplusf_(l0) + (double)softplusf_(l1);
          if (step < 4) {
            float p0 = fast_sigmoid(l0), p1 = fast_sigmoid(l1);
            uint32_t idx0 = (uint32_t)(m0 + row) * (uint32_t)HH + (uint32_t)c_loc;
            float u0 = jax_uniform01(hk0, hk1, idx0);
            float u1 = jax_uniform01(hk0, hk1, idx0 + 1u);
            __nv_bfloat162 v;
            v.x = (u0 < p0) ? onev : zerov;
            v.y = (u1 < p1) ? onev : zerov;
            uint32_t off = (uint32_t)(row * 128 + (c_loc & 63) * 2);
            *(__nv_bfloat162 *)(smem + SM_H + (c_loc >> 6) * 8192 + sw128(off)) = v;
          }
        }
      }
    }
    __syncthreads();  // h buffer visible
    if (step == 4) break;

    // ---------------- x phase: 2 producer warps, 6 consumer warps ---------
    if (wid < 2) {
      // ======== producers: per tile M64(N=2 warps x M32?) -> warp = M32xN64
      float accx[2][8][4];
      issue_bx(0); issue_bx(1);
#pragma unroll 1
      for (int tile = 0; tile < 64; tile++) {
        int s = tile & 1;
        NB_SYNC(4 + s, 256);  // wait lin[s] empty
#pragma unroll
        for (int i = 0; i < 2; i++)
#pragma unroll
          for (int j = 0; j < 8; j++)
#pragma unroll
            for (int v = 0; v < 4; v++) accx[i][j][v] = 0.0f;
#pragma unroll
        for (int kc = 0; kc < 2; kc++) {
          int g = tile * 2 + kc;
          if (g + 1 < 128) asm volatile("cp.async.wait_group 1;" ::: "memory");
          else             asm volatile("cp.async.wait_group 0;" ::: "memory");
          NB_SYNC(1, 64);  // B stage ready for both producer warps
          uint32_t abase = sb + SM_H + (uint32_t)kc * 8192;
          uint32_t bbase = sb + SM_BX + (uint32_t)(g & 1) * 16384;
#pragma unroll
          for (int kk = 0; kk < 4; kk++) {
            uint32_t a[2][4];
#pragma unroll
            for (int i = 0; i < 2; i++)
              ldsm4(a[i], abase + sw128(offA[i] + kk * 32));
#pragma unroll
            for (int p = 0; p < 2; p++) {
              uint32_t bb = bbase + 8192u * p;
#pragma unroll
              for (int jb = 0; jb < 4; jb++) {
                uint32_t b[4];
                ldsm4(b, bb + sw128(offBp[jb] + kk * 32));
#pragma unroll
                for (int i = 0; i < 2; i++) {
                  mma_bf16(accx[i][jb * 2 + 0], a[i], b[0], b[1]);
                  mma_bf16(accx[i][jb * 2 + 1], a[i], b[2], b[3]);
                }
              }
            }
          }
          NB_SYNC(1, 64);  // B stage consumed
          if (g + 2 < 128) issue_bx(g + 2);
        }
        // bias + write lin tile (fp32, pitch 264B)
        int n0 = tile * 64;
        char *lin = smem + SM_LIN + s * LIN_BUF;
#pragma unroll
        for (int j = 0; j < 8; j++) {
          float2 b2 = *(const float2 *)&bx_[n0 + j * 8 + 2 * tq];
          int col = j * 8 + 2 * tq;
#pragma unroll
          for (int i = 0; i < 2; i++) {
#pragma unroll
            for (int h = 0; h < 2; h++) {
              int row = wm * 32 + i * 16 + q + h * 8;
              float2 v;
              v.x = accx[i][j][2 * h + 0] + b2.x;
              v.y = accx[i][j][2 * h + 1] + b2.y;
              *(float2 *)(lin + row * 264 + col * 4) = v;
            }
          }
        }
        __threadfence_block();
        NB_ARRIVE(2 + s, 256);  // signal lin[s] full
      }
    } else {
      // ======== consumers (192 lanes) ========
      NB_ARRIVE(4, 256);  // prime empty[0]
      NB_ARRIVE(5, 256);  // prime empty[1]
      const int ct = t - 64;  // 0..191, warp-aligned blocks of 32
#pragma unroll 1
      for (int tile = 0; tile < 64; tile++) {
        int s = tile & 1;
        NB_SYNC(2 + s, 256);  // wait lin[s] full
        int n0 = tile * 64;
        const char *lin = smem + SM_LIN + s * LIN_BUF;
#pragma unroll 1
        for (int j2 = ct; j2 < 2048; j2 += 192) {
          int row = j2 >> 5, cc = (j2 & 31) * 2;
          float2 lv = *(const float2 *)(lin + row * 264 + cc * 4);
          float p0 = fast_sigmoid(lv.x), p1 = fast_sigmoid(lv.y);
          uint32_t idx0 =
              (uint32_t)(m0 + row) * (uint32_t)DD + (uint32_t)(n0 + cc);
          float u0 = jax_uniform01(xk0, xk1, idx0);
          float u1 = jax_uniform01(xk0, xk1, idx0 + 1u);
          bool s0 = (u0 < p0), s1 = (u1 < p1);
          if (step == 3) {
            float2 bb = *(const float2 *)&bx_[n0 + cc];
            if (s0) spb += (double)bb.x;
            if (s1) spb += (double)bb.y;
          }
          uint32_t packed = (s0 ? 0x3F80u : 0u) | (s1 ? 0x3F800000u : 0u);
          *(uint32_t *)&g_xb[(size_t)(m0 + row) * DD + n0 + cc] = packed;
        }
        if (tile < 62) NB_ARRIVE(4 + s, 256);  // free lin[s]
      }
    }
    __syncthreads();          // both groups done; named barriers drained
    issue_h(0); issue_h(1);   // prologue for next h phase
  }

  // ---------------- reductions ----------------
#pragma unroll
  for (int o = 16; o > 0; o >>= 1) {
    sp0 += __shfl_down_sync(0xffffffffu, sp0, o);
    sp1 += __shfl_down_sync(0xffffffffu, sp1, o);
    spb += __shfl_down_sync(0xffffffffu, spb, o);
  }
  if (l == 0) {
    atomicAdd(&g_acc[0], sp0);
    atomicAdd(&g_acc[1], sp1);
    atomicAdd(&g_acc[3], spb);
  }
}

// ---------------- prep (conv fuses x.bx accumulation) ----------------
__global__ void conv_kernel(const float *__restrict__ x,
                            const float *__restrict__ bx) {
  size_t n = (size_t)BB * DD / 4;
  double s = 0.0;
  for (size_t i = (size_t)blockIdx.x * blockDim.x + threadIdx.x; i < n;
       i += (size_t)gridDim.x * blockDim.x) {
    float4 v = ((const float4 *)x)[i];
    ushort4 o;
    o.x = __bfloat16_as_ushort(__float2bfloat16(v.x));
    o.y = __bfloat16_as_ushort(__float2bfloat16(v.y));
    o.z = __bfloat16_as_ushort(__float2bfloat16(v.z));
    o.w = __bfloat16_as_ushort(__float2bfloat16(v.w));
    ((ushort4 *)g_xb)[i] = o;
    uint32_t d = (uint32_t)((i * 4) & (DD - 1));
    const float4 b4 = *(const float4 *)&bx[d];
    s += (double)(v.x * b4.x + v.y * b4.y) + (double)(v.z * b4.z + v.w * b4.w);
  }
#pragma unroll
  for (int off = 16; off > 0; off >>= 1)
    s += __shfl_down_sync(0xffffffffu, s, off);
  if ((threadIdx.x & 31) == 0) atomicAdd(&g_acc[2], s);
}

__global__ void wsplit_kernel(const float *__restrict__ W) {
  int n = DD * HH;
  for (int i = blockIdx.x * blockDim.x + threadIdx.x; i < n;
       i += gridDim.x * blockDim.x) {
    float w = W[i];
    __nv_bfloat16 b0 = __float2bfloat16(w);
    float r1 = w - __bfloat162float(b0);
    __nv_bfloat16 b1 = __float2bfloat16(r1);
    g_Wx[0][i] = b0; g_Wx[1][i] = b1;
    int d = i >> 7, h = i & 127;
    int j = h * DD + d;
    g_Wh[0][j] = b0; g_Wh[1][j] = b1;
  }
}

__global__ void zero_acc_kernel() {
  if (threadIdx.x < 4) g_acc[threadIdx.x] = 0.0;
}

// cd = meanF(x) - meanF(x_rec); F = -sum softplus - v.bx
__global__ void finalize_kernel(float *out) {
  double cd = (-g_acc[0] - g_acc[2] + g_acc[1] + g_acc[3]) / (double)BB;
  out[0] = (float)cd;
}

// =============================================================
extern "C" void kernel_launch(void *const *d_in, const int *in_sizes, int n_in,
                              void *d_out, int out_size) {
  (void)in_sizes; (void)n_in; (void)out_size;
  const float *x  = (const float *)d_in[0];
  const float *W  = (const float *)d_in[1];
  const float *bx = (const float *)d_in[2];
  const float *bh = (const float *)d_in[3];

  static int attr_set = 0;
  if (!attr_set) {
    cudaFuncSetAttribute(fused_cd_kernel,
                         cudaFuncAttributeMaxDynamicSharedMemorySize, SMEM_BYTES);
    attr_set = 1;
  }

  zero_acc_kernel<<<1, 32>>>();
  conv_kernel<<<1024, 256>>>(x, bx);
  wsplit_kernel<<<2048, 256>>>(W);

  fused_cd_kernel<<<BB / 64, 256, SMEM_BYTES>>>(bx, bh);

  finalize_kernel<<<1, 1>>>((float *)d_out);
}

// round 12
// speedup vs baseline: 1.2437x; 1.2437x over previous
#include <cuda_runtime.h>
#include <cuda_bf16.h>
#include <cstdint>
#include <math.h>

#define BB 16384
#define DD 4096
#define HH 128

// ---------------- scratch ----------------
__device__ __nv_bfloat16 g_xb[(size_t)BB * DD];     // visible sample (in-place chain)
__device__ __nv_bfloat16 g_hb[(size_t)BB * HH];     // hidden sample
__device__ __nv_bfloat16 g_Wx[2][(size_t)DD * HH];  // W splits, [d][h] (x-pass B)
__device__ __nv_bfloat16 g_Wh[2][(size_t)DD * HH];  // W splits, [h][d] (h-pass B)
__device__ double g_acc[4];

// ---------------- threefry2x32 (JAX-exact, verified R1-R10) ----------------
__host__ __device__ __forceinline__ uint32_t rotl32(uint32_t v, int s) {
  return (v << s) | (v >> (32 - s));
}
__host__ __device__ __forceinline__ void tf2x32(uint32_t k0, uint32_t k1,
                                                uint32_t x0, uint32_t x1,
                                                uint32_t &o0, uint32_t &o1) {
  uint32_t ks2 = k0 ^ k1 ^ 0x1BD11BDAu;
  x0 += k0; x1 += k1;
#define TF_R(r) { x0 += x1; x1 = rotl32(x1, r); x1 ^= x0; }
  TF_R(13) TF_R(15) TF_R(26) TF_R(6)   x0 += k1;  x1 += ks2 + 1u;
  TF_R(17) TF_R(29) TF_R(16) TF_R(24)  x0 += ks2; x1 += k0 + 2u;
  TF_R(13) TF_R(15) TF_R(26) TF_R(6)   x0 += k0;  x1 += k1 + 3u;
  TF_R(17) TF_R(29) TF_R(16) TF_R(24)  x0 += k1;  x1 += ks2 + 4u;
  TF_R(13) TF_R(15) TF_R(26) TF_R(6)   x0 += ks2; x1 += k0 + 5u;
#undef TF_R
  o0 = x0; o1 = x1;
}
__device__ __forceinline__ float jax_uniform01(uint32_t k0, uint32_t k1, uint32_t idx) {
  uint32_t a, b;
  tf2x32(k0, k1, 0u, idx, a, b);
  uint32_t bits = a ^ b;
  return __uint_as_float((bits >> 9) | 0x3F800000u) - 1.0f;
}
__device__ __forceinline__ float fast_sigmoid(float x) {
  float e, r;
  asm("ex2.approx.f32 %0, %1;" : "=f"(e) : "f"(-1.4426950408889634f * x));
  asm("rcp.approx.f32 %0, %1;" : "=f"(r) : "f"(1.0f + e));
  return r;
}
__device__ __forceinline__ float softplusf_(float x) {
  return fmaxf(x, 0.0f) + log1pf(expf(-fabsf(x)));
}

// ---------------- PTX helpers (baseline sm_100-safe) ----------------
__device__ __forceinline__ uint32_t smem_u32(const void *p) {
  uint32_t a;
  asm("{ .reg .u64 t; cvta.to.shared.u64 t, %1; cvt.u32.u64 %0, t; }"
      : "=r"(a) : "l"(p));
  return a;
}
__device__ __forceinline__ void ldsm4(uint32_t *r, uint32_t a) {
  asm volatile("ldmatrix.sync.aligned.m8n8.x4.shared.b16 {%0,%1,%2,%3}, [%4];"
               : "=r"(r[0]), "=r"(r[1]), "=r"(r[2]), "=r"(r[3]) : "r"(a));
}
__device__ __forceinline__ void mma_bf16(float *c, const uint32_t *a,
                                         uint32_t b0, uint32_t b1) {
  asm volatile(
      "mma.sync.aligned.m16n8k16.row.col.f32.bf16.bf16.f32 "
      "{%0,%1,%2,%3}, {%4,%5,%6,%7}, {%8,%9}, {%0,%1,%2,%3};"
      : "+f"(c[0]), "+f"(c[1]), "+f"(c[2]), "+f"(c[3])
      : "r"(a[0]), "r"(a[1]), "r"(a[2]), "r"(a[3]), "r"(b0), "r"(b1));
}
__device__ __forceinline__ uint32_t sw128(uint32_t o) {
  return o ^ ((o >> 3) & 0x70);
}

// load [ROWS x 64 bf16] tile, 128B rows, SW128-swizzled, via cp.async
template <int LD, int ROWS>
__device__ __forceinline__ void load_tile(uint32_t sdst, const __nv_bfloat16 *g,
                                          int row0, int kt) {
  int t = threadIdx.x;
#pragma unroll
  for (int i = 0; i < ROWS / 32; i++) {
    int idx = t + 256 * i;
    int r = idx >> 3, c = idx & 7;
    uint32_t sw = sw128((uint32_t)(r * 128 + c * 16));
    const void *ga = (const void *)(g + (size_t)(row0 + r) * LD + kt + c * 8);
    asm volatile("cp.async.cg.shared.global [%0], [%1], 16;"
                 :: "r"(sdst + sw), "l"(ga));
  }
}

// =============================================================
// h-pass: lin = x @ W + bh   M=16384 N=128 K=4096 (2 splits)
// CTA tile 128x128, BK=64, double-buffered; 2 CTAs/SM.
// Warps 4(M)x2(N): warp tile M32 x N64. acc[2][8][4].
// smem: 2 stages x 49152 (A 16KB @0, B split p 16KB @16384+p*16384)
// =============================================================
static constexpr int H_STAGE = 49152;
static constexpr int H_SMEM = 2 * H_STAGE;  // 98304

__global__ void __launch_bounds__(256, 2)
gemm_h_kernel(const float *__restrict__ bh_, uint32_t k0, uint32_t k1,
              int do_sample, int acc_slot) {
  extern __shared__ char smem[];
  uint32_t sb = smem_u32(smem);
  const int t = threadIdx.x, wid = t >> 5, l = t & 31;
  const int wm = wid & 3, wn = wid >> 2;
  const int m0 = blockIdx.x * 128;
  const int q = l >> 2, tq = l & 3;

  uint32_t offA[2], offB[4];
#pragma unroll
  for (int i = 0; i < 2; i++)
    offA[i] = (uint32_t)((wm * 32 + i * 16 + (l & 15)) * 128 + ((l >> 4) & 1) * 16);
#pragma unroll
  for (int jb = 0; jb < 4; jb++)
    offB[jb] = (uint32_t)((wn * 64 + jb * 16 + (l & 7) + ((l >> 4) & 1) * 8) * 128 +
                          ((l >> 3) & 1) * 16);

  float acc[2][8][4];
#pragma unroll
  for (int i = 0; i < 2; i++)
#pragma unroll
    for (int j = 0; j < 8; j++)
#pragma unroll
      for (int v = 0; v < 4; v++) acc[i][j][v] = 0.0f;

  auto issue_load = [&](int c) {
    int s = c & 1, kt = c * 64;
    uint32_t base = sb + s * H_STAGE;
    load_tile<DD, 128>(base, g_xb, m0, kt);
#pragma unroll
    for (int p = 0; p < 2; p++)
      load_tile<DD, 128>(base + 16384 + 16384 * p, g_Wh[p], 0, kt);
    asm volatile("cp.async.commit_group;" ::: "memory");
  };

  issue_load(0); issue_load(1);

#pragma unroll 1
  for (int c = 0; c < 64; c++) {
    if (c + 1 < 64) asm volatile("cp.async.wait_group 1;" ::: "memory");
    else            asm volatile("cp.async.wait_group 0;" ::: "memory");
    __syncthreads();
    uint32_t base = sb + (uint32_t)(c & 1) * H_STAGE;
#pragma unroll
    for (int kk = 0; kk < 4; kk++) {
      uint32_t a[2][4];
#pragma unroll
      for (int i = 0; i < 2; i++)
        ldsm4(a[i], base + sw128(offA[i] + kk * 32));
#pragma unroll
      for (int p = 0; p < 2; p++) {
        uint32_t bb = base + 16384u + 16384u * p;
#pragma unroll
        for (int jb = 0; jb < 4; jb++) {
          uint32_t b[4];
          ldsm4(b, bb + sw128(offB[jb] + kk * 32));
#pragma unroll
          for (int i = 0; i < 2; i++) {
            mma_bf16(acc[i][jb * 2 + 0], a[i], b[0], b[1]);
            mma_bf16(acc[i][jb * 2 + 1], a[i], b[2], b[3]);
          }
        }
      }
    }
    __syncthreads();
    if (c + 2 < 64) issue_load(c + 2);
  }

  // epilogue: bias + softplus and/or threefry sample into g_hb
  double sp = 0.0;
  const __nv_bfloat16 onev = __float2bfloat16(1.0f);
  const __nv_bfloat16 zerov = __float2bfloat16(0.0f);
#pragma unroll
  for (int j = 0; j < 8; j++) {
    float2 b2 = *(const float2 *)&bh_[wn * 64 + j * 8 + 2 * tq];
    int col = wn * 64 + j * 8 + 2 * tq;
#pragma unroll
    for (int i = 0; i < 2; i++) {
#pragma unroll
      for (int h = 0; h < 2; h++) {
        int gr = m0 + wm * 32 + i * 16 + q + h * 8;
        float l0 = acc[i][j][2 * h + 0] + b2.x;
        float l1 = acc[i][j][2 * h + 1] + b2.y;
        if (acc_slot >= 0)
          sp += (double)softplusf_(l0) + (double)softplusf_(l1);
        if (do_sample) {
          float p0 = fast_sigmoid(l0), p1 = fast_sigmoid(l1);
          uint32_t idx0 = (uint32_t)gr * (uint32_t)HH + (uint32_t)col;
          float u0 = jax_uniform01(k0, k1, idx0);
          float u1 = jax_uniform01(k0, k1, idx0 + 1u);
          __nv_bfloat162 v;
          v.x = (u0 < p0) ? onev : zerov;
          v.y = (u1 < p1) ? onev : zerov;
          *(__nv_bfloat162 *)&g_hb[(size_t)gr * HH + col] = v;
        }
      }
    }
  }
  if (acc_slot >= 0) {
#pragma unroll
    for (int o = 16; o > 0; o >>= 1) sp += __shfl_down_sync(0xffffffffu, sp, o);
    if (l == 0) atomicAdd(&g_acc[acc_slot], sp);
  }
}

// =============================================================
// x-pass: lin = h @ W^T + bx   M=16384 N=4096 K=128 (2 splits)
// CTA tile 64(M) x 64(N); 3 CTAs/SM; all loads upfront (no pipeline).
// Warps 2(M)x4(N): warp tile M32 x N16. acc[2][2][4].
// smem: A 2x8KB @0; B @16384: chunk kc at +kc*16384, split p at +p*8192;
//       staging @49152: 64 rows x 136B (8-aligned pitch).
// =============================================================
static constexpr int X_STG_PITCH = 136;
static constexpr int X_SMEM = 49152 + 64 * X_STG_PITCH;  // 57856

__global__ void __launch_bounds__(256, 3)
gemm_x_kernel(const float *__restrict__ bx_, uint32_t k0, uint32_t k1,
              int bx_slot) {
  extern __shared__ char smem[];
  uint32_t sb = smem_u32(smem);
  const int t = threadIdx.x, wid = t >> 5, l = t & 31;
  const int wm = wid & 1, wn = wid >> 1;
  const int m0 = blockIdx.x * 64, n0 = blockIdx.y * 64;
  const int q = l >> 2, tq = l & 3;

  uint32_t offA[2], offB;
#pragma unroll
  for (int i = 0; i < 2; i++)
    offA[i] = (uint32_t)((wm * 32 + i * 16 + (l & 15)) * 128 + ((l >> 4) & 1) * 16);
  offB = (uint32_t)((wn * 16 + (l & 7) + ((l >> 4) & 1) * 8) * 128 +
                    ((l >> 3) & 1) * 16);

  // all loads upfront (K=128 -> 2 chunks)
#pragma unroll
  for (int kc = 0; kc < 2; kc++) {
    load_tile<HH, 64>(sb + kc * 8192, g_hb, m0, kc * 64);
#pragma unroll
    for (int p = 0; p < 2; p++)
      load_tile<HH, 64>(sb + 16384 + kc * 16384 + p * 8192, g_Wx[p], n0, kc * 64);
  }
  asm volatile("cp.async.commit_group;" ::: "memory");

  float acc[2][2][4];
#pragma unroll
  for (int i = 0; i < 2; i++)
#pragma unroll
    for (int j = 0; j < 2; j++)
#pragma unroll
      for (int v = 0; v < 4; v++) acc[i][j][v] = 0.0f;

  asm volatile("cp.async.wait_group 0;" ::: "memory");
  __syncthreads();

#pragma unroll
  for (int kc = 0; kc < 2; kc++) {
    uint32_t abase = sb + (uint32_t)kc * 8192;
    uint32_t bbase = sb + 16384u + (uint32_t)kc * 16384;
#pragma unroll
    for (int kk = 0; kk < 4; kk++) {
      uint32_t a[2][4];
#pragma unroll
      for (int i = 0; i < 2; i++)
        ldsm4(a[i], abase + sw128(offA[i] + kk * 32));
#pragma unroll
      for (int p = 0; p < 2; p++) {
        uint32_t b[4];
        ldsm4(b, bbase + p * 8192u + sw128(offB + kk * 32));
#pragma unroll
        for (int i = 0; i < 2; i++) {
          mma_bf16(acc[i][0], a[i], b[0], b[1]);
          mma_bf16(acc[i][1], a[i], b[2], b[3]);
        }
      }
    }
  }

  // epilogue: bias + threefry sample -> staging -> coalesced store
  double spb = 0.0;
  const __nv_bfloat16 onev = __float2bfloat16(1.0f);
  const __nv_bfloat16 zerov = __float2bfloat16(0.0f);
  char *stg = smem + 49152;
#pragma unroll
  for (int j = 0; j < 2; j++) {
    int col = wn * 16 + j * 8 + 2 * tq;
    float2 b2 = *(const float2 *)&bx_[n0 + col];
#pragma unroll
    for (int i = 0; i < 2; i++) {
#pragma unroll
      for (int h = 0; h < 2; h++) {
        int row = wm * 32 + i * 16 + q + h * 8;
        float l0 = acc[i][j][2 * h + 0] + b2.x;
        float l1 = acc[i][j][2 * h + 1] + b2.y;
        float p0 = fast_sigmoid(l0), p1 = fast_sigmoid(l1);
        uint32_t idx0 = (uint32_t)(m0 + row) * (uint32_t)DD + (uint32_t)(n0 + col);
        float u0 = jax_uniform01(k0, k1, idx0);
        float u1 = jax_uniform01(k0, k1, idx0 + 1u);
        bool s0 = (u0 < p0), s1 = (u1 < p1);
        if (bx_slot >= 0) {
          if (s0) spb += (double)b2.x;
          if (s1) spb += (double)b2.y;
        }
        __nv_bfloat162 v;
        v.x = s0 ? onev : zerov;
        v.y = s1 ? onev : zerov;
        *(__nv_bfloat162 *)(stg + row * X_STG_PITCH + col * 2) = v;
      }
    }
  }
  if (bx_slot >= 0) {
#pragma unroll
    for (int o = 16; o > 0; o >>= 1) spb += __shfl_down_sync(0xffffffffu, spb, o);
    if (l == 0) atomicAdd(&g_acc[bx_slot], spb);
  }
  __syncthreads();
#pragma unroll
  for (int i2 = 0; i2 < 4; i2++) {
    int idx = t + 256 * i2;
    int rr = idx >> 4, c8 = idx & 15;
    uint64_t v = *(const uint64_t *)(stg + rr * X_STG_PITCH + c8 * 8);
    *(uint64_t *)&g_xb[(size_t)(m0 + rr) * DD + n0 + c8 * 4] = v;
  }
}

// ---------------- prep (conv fuses x.bx accumulation) ----------------
__global__ void conv_kernel(const float *__restrict__ x,
                            const float *__restrict__ bx) {
  size_t n = (size_t)BB * DD / 4;
  double s = 0.0;
  for (size_t i = (size_t)blockIdx.x * blockDim.x + threadIdx.x; i < n;
       i += (size_t)gridDim.x * blockDim.x) {
    float4 v = ((const float4 *)x)[i];
    ushort4 o;
    o.x = __bfloat16_as_ushort(__float2bfloat16(v.x));
    o.y = __bfloat16_as_ushort(__float2bfloat16(v.y));
    o.z = __bfloat16_as_ushort(__float2bfloat16(v.z));
    o.w = __bfloat16_as_ushort(__float2bfloat16(v.w));
    ((ushort4 *)g_xb)[i] = o;
    uint32_t d = (uint32_t)((i * 4) & (DD - 1));
    const float4 b4 = *(const float4 *)&bx[d];
    s += (double)(v.x * b4.x + v.y * b4.y) + (double)(v.z * b4.z + v.w * b4.w);
  }
#pragma unroll
  for (int off = 16; off > 0; off >>= 1)
    s += __shfl_down_sync(0xffffffffu, s, off);
  if ((threadIdx.x & 31) == 0) atomicAdd(&g_acc[2], s);
}

__global__ void wsplit_kernel(const float *__restrict__ W) {
  int n = DD * HH;
  for (int i = blockIdx.x * blockDim.x + threadIdx.x; i < n;
       i += gridDim.x * blockDim.x) {
    float w = W[i];
    __nv_bfloat16 b0 = __float2bfloat16(w);
    float r1 = w - __bfloat162float(b0);
    __nv_bfloat16 b1 = __float2bfloat16(r1);
    g_Wx[0][i] = b0; g_Wx[1][i] = b1;
    int d = i >> 7, h = i & 127;
    int j = h * DD + d;
    g_Wh[0][j] = b0; g_Wh[1][j] = b1;
  }
}

__global__ void zero_acc_kernel() {
  if (threadIdx.x < 4) g_acc[threadIdx.x] = 0.0;
}

// cd = meanF(x) - meanF(x_rec); F = -sum softplus - v.bx
__global__ void finalize_kernel(float *out) {
  double cd = (-g_acc[0] - g_acc[2] + g_acc[1] + g_acc[3]) / (double)BB;
  out[0] = (float)cd;
}

// =============================================================
extern "C" void kernel_launch(void *const *d_in, const int *in_sizes, int n_in,
                              void *d_out, int out_size) {
  (void)in_sizes; (void)n_in; (void)out_size;
  const float *x  = (const float *)d_in[0];
  const float *W  = (const float *)d_in[1];
  const float *bx = (const float *)d_in[2];
  const float *bh = (const float *)d_in[3];

  static int attr_set = 0;
  if (!attr_set) {
    cudaFuncSetAttribute(gemm_h_kernel,
                         cudaFuncAttributeMaxDynamicSharedMemorySize, H_SMEM);
    cudaFuncSetAttribute(gemm_x_kernel,
                         cudaFuncAttributeMaxDynamicSharedMemorySize, X_SMEM);
    attr_set = 1;
  }

  zero_acc_kernel<<<1, 32>>>();
  conv_kernel<<<1024, 256>>>(x, bx);
  wsplit_kernel<<<2048, 256>>>(W);

  dim3 grdh(BB / 128, 1);
  dim3 grdx(BB / 64, DD / 64);

  for (int i = 0; i < 4; i++) {
    uint32_t h0, h1, xk0, xk1;
    tf2x32(0u, 42u, 0u, (uint32_t)(2 * i),     h0,  h1);
    tf2x32(0u, 42u, 0u, (uint32_t)(2 * i + 1), xk0, xk1);
    gemm_h_kernel<<<grdh, 256, H_SMEM>>>(bh, h0, h1, /*sample=*/1,
                                         /*slot=*/(i == 0) ? 0 : -1);
    gemm_x_kernel<<<grdx, 256, X_SMEM>>>(bx, xk0, xk1,
                                         /*bx_slot=*/(i == 3) ? 3 : -1);
  }
  // F(x_rec) softplus term
  gemm_h_kernel<<<grdh, 256, H_SMEM>>>(bh, 0u, 0u, /*sample=*/0, /*slot=*/1);

  finalize_kernel<<<1, 1>>>((float *)d_out);
}

// round 13
// speedup vs baseline: 1.3197x; 1.0611x over previous
#include <cuda_runtime.h>
#include <cuda_bf16.h>
#include <cstdint>
#include <math.h>

#define BB 16384
#define DD 4096
#define HH 128

// ---------------- scratch ----------------
__device__ __nv_bfloat16 g_xb[(size_t)BB * DD];     // visible sample (in-place chain)
__device__ __nv_bfloat16 g_hb[(size_t)BB * HH];     // hidden sample
__device__ __nv_bfloat16 g_Wx[2][(size_t)DD * HH];  // W splits, [d][h] (x-pass B)
__device__ __nv_bfloat16 g_Wh[2][(size_t)DD * HH];  // W splits, [h][d] (h-pass B)
__device__ double g_acc[4];

// ---------------- threefry2x32 (JAX-exact, verified R1-R12) ----------------
__host__ __device__ __forceinline__ uint32_t rotl32(uint32_t v, int s) {
  return (v << s) | (v >> (32 - s));
}
__host__ __device__ __forceinline__ void tf2x32(uint32_t k0, uint32_t k1,
                                                uint32_t x0, uint32_t x1,
                                                uint32_t &o0, uint32_t &o1) {
  uint32_t ks2 = k0 ^ k1 ^ 0x1BD11BDAu;
  x0 += k0; x1 += k1;
#define TF_R(r) { x0 += x1; x1 = rotl32(x1, r); x1 ^= x0; }
  TF_R(13) TF_R(15) TF_R(26) TF_R(6)   x0 += k1;  x1 += ks2 + 1u;
  TF_R(17) TF_R(29) TF_R(16) TF_R(24)  x0 += ks2; x1 += k0 + 2u;
  TF_R(13) TF_R(15) TF_R(26) TF_R(6)   x0 += k0;  x1 += k1 + 3u;
  TF_R(17) TF_R(29) TF_R(16) TF_R(24)  x0 += k1;  x1 += ks2 + 4u;
  TF_R(13) TF_R(15) TF_R(26) TF_R(6)   x0 += ks2; x1 += k0 + 5u;
#undef TF_R
  o0 = x0; o1 = x1;
}
__device__ __forceinline__ float jax_uniform01(uint32_t k0, uint32_t k1, uint32_t idx) {
  uint32_t a, b;
  tf2x32(k0, k1, 0u, idx, a, b);
  uint32_t bits = a ^ b;
  return __uint_as_float((bits >> 9) | 0x3F800000u) - 1.0f;
}
__device__ __forceinline__ float fast_sigmoid(float x) {
  float e, r;
  asm("ex2.approx.f32 %0, %1;" : "=f"(e) : "f"(-1.4426950408889634f * x));
  asm("rcp.approx.f32 %0, %1;" : "=f"(r) : "f"(1.0f + e));
  return r;
}
__device__ __forceinline__ float softplusf_(float x) {
  return fmaxf(x, 0.0f) + log1pf(expf(-fabsf(x)));
}

// ---------------- PTX helpers (baseline sm_100-safe) ----------------
__device__ __forceinline__ uint32_t smem_u32(const void *p) {
  uint32_t a;
  asm("{ .reg .u64 t; cvta.to.shared.u64 t, %1; cvt.u32.u64 %0, t; }"
      : "=r"(a) : "l"(p));
  return a;
}
__device__ __forceinline__ void ldsm4(uint32_t *r, uint32_t a) {
  asm volatile("ldmatrix.sync.aligned.m8n8.x4.shared.b16 {%0,%1,%2,%3}, [%4];"
               : "=r"(r[0]), "=r"(r[1]), "=r"(r[2]), "=r"(r[3]) : "r"(a));
}
__device__ __forceinline__ void mma_bf16(float *c, const uint32_t *a,
                                         uint32_t b0, uint32_t b1) {
  asm volatile(
      "mma.sync.aligned.m16n8k16.row.col.f32.bf16.bf16.f32 "
      "{%0,%1,%2,%3}, {%4,%5,%6,%7}, {%8,%9}, {%0,%1,%2,%3};"
      : "+f"(c[0]), "+f"(c[1]), "+f"(c[2]), "+f"(c[3])
      : "r"(a[0]), "r"(a[1]), "r"(a[2]), "r"(a[3]), "r"(b0), "r"(b1));
}
__device__ __forceinline__ uint32_t sw128(uint32_t o) {
  return o ^ ((o >> 3) & 0x70);
}

// load [ROWS x 64 bf16] tile, 128B rows, SW128-swizzled, via cp.async
template <int LD, int ROWS>
__device__ __forceinline__ void load_tile(uint32_t sdst, const __nv_bfloat16 *g,
                                          int row0, int kt) {
  int t = threadIdx.x;
#pragma unroll
  for (int i = 0; i < ROWS / 32; i++) {
    int idx = t + 256 * i;
    int r = idx >> 3, c = idx & 7;
    uint32_t sw = sw128((uint32_t)(r * 128 + c * 16));
    const void *ga = (const void *)(g + (size_t)(row0 + r) * LD + kt + c * 8);
    asm volatile("cp.async.cg.shared.global [%0], [%1], 16;"
                 :: "r"(sdst + sw), "l"(ga));
  }
}

// =============================================================
// h-pass (R5 config): lin = x @ W + bh   M=16384 N=128 K=4096 (2 splits)
// CTA tile 64x128, BK=64, double-buffered; grid 256 -> 2 CTAs/SM.
// Warps 2(M)x4(N): warp tile M32 x N32. acc[2][4][4].
// smem: 2 stages x 40960 (A 8KB @0, B split p 16KB @8192+p*16384)
// =============================================================
static constexpr int H_STAGE = 40960;
static constexpr int H_SMEM = 2 * H_STAGE;  // 81920

__global__ void __launch_bounds__(256, 2)
gemm_h_kernel(const float *__restrict__ bh_, uint32_t k0, uint32_t k1,
              int do_sample, int acc_slot) {
  extern __shared__ char smem[];
  uint32_t sb = smem_u32(smem);
  const int t = threadIdx.x, wid = t >> 5, l = t & 31;
  const int wm = wid & 1, wn = wid >> 1;
  const int m0 = blockIdx.x * 64;
  const int q = l >> 2, tq = l & 3;

  uint32_t offA[2], offB[2];
#pragma unroll
  for (int i = 0; i < 2; i++)
    offA[i] = (uint32_t)((wm * 32 + i * 16 + (l & 15)) * 128 + ((l >> 4) & 1) * 16);
#pragma unroll
  for (int jb = 0; jb < 2; jb++)
    offB[jb] = (uint32_t)((wn * 32 + jb * 16 + (l & 7) + ((l >> 4) & 1) * 8) * 128 +
                          ((l >> 3) & 1) * 16);

  float acc[2][4][4];
#pragma unroll
  for (int i = 0; i < 2; i++)
#pragma unroll
    for (int j = 0; j < 4; j++)
#pragma unroll
      for (int v = 0; v < 4; v++) acc[i][j][v] = 0.0f;

  auto issue_load = [&](int c) {
    int s = c & 1, kt = c * 64;
    uint32_t base = sb + s * H_STAGE;
    load_tile<DD, 64>(base, g_xb, m0, kt);
#pragma unroll
    for (int p = 0; p < 2; p++)
      load_tile<DD, 128>(base + 8192 + 16384 * p, g_Wh[p], 0, kt);
    asm volatile("cp.async.commit_group;" ::: "memory");
  };

  issue_load(0); issue_load(1);

#pragma unroll 1
  for (int c = 0; c < 64; c++) {
    if (c + 1 < 64) asm volatile("cp.async.wait_group 1;" ::: "memory");
    else            asm volatile("cp.async.wait_group 0;" ::: "memory");
    __syncthreads();
    uint32_t base = sb + (uint32_t)(c & 1) * H_STAGE;
#pragma unroll
    for (int kk = 0; kk < 4; kk++) {
      uint32_t a[2][4];
#pragma unroll
      for (int i = 0; i < 2; i++)
        ldsm4(a[i], base + sw128(offA[i] + kk * 32));
#pragma unroll
      for (int p = 0; p < 2; p++) {
        uint32_t bb = base + 8192u + 16384u * p;
#pragma unroll
        for (int jb = 0; jb < 2; jb++) {
          uint32_t b[4];
          ldsm4(b, bb + sw128(offB[jb] + kk * 32));
#pragma unroll
          for (int i = 0; i < 2; i++) {
            mma_bf16(acc[i][jb * 2 + 0], a[i], b[0], b[1]);
            mma_bf16(acc[i][jb * 2 + 1], a[i], b[2], b[3]);
          }
        }
      }
    }
    __syncthreads();
    if (c + 2 < 64) issue_load(c + 2);
  }

  // epilogue: bias + softplus and/or threefry sample into g_hb
  double sp = 0.0;
  const __nv_bfloat16 onev = __float2bfloat16(1.0f);
  const __nv_bfloat16 zerov = __float2bfloat16(0.0f);
#pragma unroll
  for (int i = 0; i < 2; i++) {
#pragma unroll
    for (int j = 0; j < 4; j++) {
      int col = wn * 32 + j * 8 + 2 * tq;
      float2 b2 = *(const float2 *)&bh_[col];
#pragma unroll
      for (int h = 0; h < 2; h++) {
        int gr = m0 + wm * 32 + i * 16 + q + h * 8;
        float l0 = acc[i][j][2 * h + 0] + b2.x;
        float l1 = acc[i][j][2 * h + 1] + b2.y;
        if (acc_slot >= 0)
          sp += (double)softplusf_(l0) + (double)softplusf_(l1);
        if (do_sample) {
          float p0 = fast_sigmoid(l0), p1 = fast_sigmoid(l1);
          uint32_t idx0 = (uint32_t)gr * (uint32_t)HH + (uint32_t)col;
          float u0 = jax_uniform01(k0, k1, idx0);
          float u1 = jax_uniform01(k0, k1, idx0 + 1u);
          __nv_bfloat162 v;
          v.x = (u0 < p0) ? onev : zerov;
          v.y = (u1 < p1) ? onev : zerov;
          *(__nv_bfloat162 *)&g_hb[(size_t)gr * HH + col] = v;
        }
      }
    }
  }
  if (acc_slot >= 0) {
#pragma unroll
    for (int o = 16; o > 0; o >>= 1) sp += __shfl_down_sync(0xffffffffu, sp, o);
    if (l == 0) atomicAdd(&g_acc[acc_slot], sp);
  }
}

// =============================================================
// x-pass (R12 config): lin = h @ W^T + bx   M=16384 N=4096 K=128 (2 splits)
// CTA tile 64(M) x 64(N); 3 CTAs/SM; all loads upfront (no pipeline).
// Warps 2(M)x4(N): warp tile M32 x N16. acc[2][2][4].
// smem: A 2x8KB @0; B @16384: chunk kc at +kc*16384, split p at +p*8192;
//       staging @49152: 64 rows x 136B (8-aligned pitch).
// =============================================================
static constexpr int X_STG_PITCH = 136;
static constexpr int X_SMEM = 49152 + 64 * X_STG_PITCH;  // 57856

__global__ void __launch_bounds__(256, 3)
gemm_x_kernel(const float *__restrict__ bx_, uint32_t k0, uint32_t k1,
              int bx_slot) {
  extern __shared__ char smem[];
  uint32_t sb = smem_u32(smem);
  const int t = threadIdx.x, wid = t >> 5, l = t & 31;
  const int wm = wid & 1, wn = wid >> 1;
  const int m0 = blockIdx.x * 64, n0 = blockIdx.y * 64;
  const int q = l >> 2, tq = l & 3;

  uint32_t offA[2], offB;
#pragma unroll
  for (int i = 0; i < 2; i++)
    offA[i] = (uint32_t)((wm * 32 + i * 16 + (l & 15)) * 128 + ((l >> 4) & 1) * 16);
  offB = (uint32_t)((wn * 16 + (l & 7) + ((l >> 4) & 1) * 8) * 128 +
                    ((l >> 3) & 1) * 16);

  // all loads upfront (K=128 -> 2 chunks)
#pragma unroll
  for (int kc = 0; kc < 2; kc++) {
    load_tile<HH, 64>(sb + kc * 8192, g_hb, m0, kc * 64);
#pragma unroll
    for (int p = 0; p < 2; p++)
      load_tile<HH, 64>(sb + 16384 + kc * 16384 + p * 8192, g_Wx[p], n0, kc * 64);
  }
  asm volatile("cp.async.commit_group;" ::: "memory");

  float acc[2][2][4];
#pragma unroll
  for (int i = 0; i < 2; i++)
#pragma unroll
    for (int j = 0; j < 2; j++)
#pragma unroll
      for (int v = 0; v < 4; v++) acc[i][j][v] = 0.0f;

  asm volatile("cp.async.wait_group 0;" ::: "memory");
  __syncthreads();

#pragma unroll
  for (int kc = 0; kc < 2; kc++) {
    uint32_t abase = sb + (uint32_t)kc * 8192;
    uint32_t bbase = sb + 16384u + (uint32_t)kc * 16384;
#pragma unroll
    for (int kk = 0; kk < 4; kk++) {
      uint32_t a[2][4];
#pragma unroll
      for (int i = 0; i < 2; i++)
        ldsm4(a[i], abase + sw128(offA[i] + kk * 32));
#pragma unroll
      for (int p = 0; p < 2; p++) {
        uint32_t b[4];
        ldsm4(b, bbase + p * 8192u + sw128(offB + kk * 32));
#pragma unroll
        for (int i = 0; i < 2; i++) {
          mma_bf16(acc[i][0], a[i], b[0], b[1]);
          mma_bf16(acc[i][1], a[i], b[2], b[3]);
        }
      }
    }
  }

  // epilogue: bias + threefry sample -> staging -> coalesced store
  double spb = 0.0;
  const __nv_bfloat16 onev = __float2bfloat16(1.0f);
  const __nv_bfloat16 zerov = __float2bfloat16(0.0f);
  char *stg = smem + 49152;
#pragma unroll
  for (int j = 0; j < 2; j++) {
    int col = wn * 16 + j * 8 + 2 * tq;
    float2 b2 = *(const float2 *)&bx_[n0 + col];
#pragma unroll
    for (int i = 0; i < 2; i++) {
#pragma unroll
      for (int h = 0; h < 2; h++) {
        int row = wm * 32 + i * 16 + q + h * 8;
        float l0 = acc[i][j][2 * h + 0] + b2.x;
        float l1 = acc[i][j][2 * h + 1] + b2.y;
        float p0 = fast_sigmoid(l0), p1 = fast_sigmoid(l1);
        uint32_t idx0 = (uint32_t)(m0 + row) * (uint32_t)DD + (uint32_t)(n0 + col);
        float u0 = jax_uniform01(k0, k1, idx0);
        float u1 = jax_uniform01(k0, k1, idx0 + 1u);
        bool s0 = (u0 < p0), s1 = (u1 < p1);
        if (bx_slot >= 0) {
          if (s0) spb += (double)b2.x;
          if (s1) spb += (double)b2.y;
        }
        __nv_bfloat162 v;
        v.x = s0 ? onev : zerov;
        v.y = s1 ? onev : zerov;
        *(__nv_bfloat162 *)(stg + row * X_STG_PITCH + col * 2) = v;
      }
    }
  }
  if (bx_slot >= 0) {
#pragma unroll
    for (int o = 16; o > 0; o >>= 1) spb += __shfl_down_sync(0xffffffffu, spb, o);
    if (l == 0) atomicAdd(&g_acc[bx_slot], spb);
  }
  __syncthreads();
#pragma unroll
  for (int i2 = 0; i2 < 4; i2++) {
    int idx = t + 256 * i2;
    int rr = idx >> 4, c8 = idx & 15;
    uint64_t v = *(const uint64_t *)(stg + rr * X_STG_PITCH + c8 * 8);
    *(uint64_t *)&g_xb[(size_t)(m0 + rr) * DD + n0 + c8 * 4] = v;
  }
}

// ---------------- prep (conv fuses x.bx accumulation) ----------------
__global__ void conv_kernel(const float *__restrict__ x,
                            const float *__restrict__ bx) {
  size_t n = (size_t)BB * DD / 4;
  double s = 0.0;
  for (size_t i = (size_t)blockIdx.x * blockDim.x + threadIdx.x; i < n;
       i += (size_t)gridDim.x * blockDim.x) {
    float4 v = ((const float4 *)x)[i];
    ushort4 o;
    o.x = __bfloat16_as_ushort(__float2bfloat16(v.x));
    o.y = __bfloat16_as_ushort(__float2bfloat16(v.y));
    o.z = __bfloat16_as_ushort(__float2bfloat16(v.z));
    o.w = __bfloat16_as_ushort(__float2bfloat16(v.w));
    ((ushort4 *)g_xb)[i] = o;
    uint32_t d = (uint32_t)((i * 4) & (DD - 1));
    const float4 b4 = *(const float4 *)&bx[d];
    s += (double)(v.x * b4.x + v.y * b4.y) + (double)(v.z * b4.z + v.w * b4.w);
  }
#pragma unroll
  for (int off = 16; off > 0; off >>= 1)
    s += __shfl_down_sync(0xffffffffu, s, off);
  if ((threadIdx.x & 31) == 0) atomicAdd(&g_acc[2], s);
}

__global__ void wsplit_kernel(const float *__restrict__ W) {
  int n = DD * HH;
  for (int i = blockIdx.x * blockDim.x + threadIdx.x; i < n;
       i += gridDim.x * blockDim.x) {
    float w = W[i];
    __nv_bfloat16 b0 = __float2bfloat16(w);
    float r1 = w - __bfloat162float(b0);
    __nv_bfloat16 b1 = __float2bfloat16(r1);
    g_Wx[0][i] = b0; g_Wx[1][i] = b1;
    int d = i >> 7, h = i & 127;
    int j = h * DD + d;
    g_Wh[0][j] = b0; g_Wh[1][j] = b1;
  }
}

__global__ void zero_acc_kernel() {
  if (threadIdx.x < 4) g_acc[threadIdx.x] = 0.0;
}

// cd = meanF(x) - meanF(x_rec); F = -sum softplus - v.bx
__global__ void finalize_kernel(float *out) {
  double cd = (-g_acc[0] - g_acc[2] + g_acc[1] + g_acc[3]) / (double)BB;
  out[0] = (float)cd;
}

// =============================================================
extern "C" void kernel_launch(void *const *d_in, const int *in_sizes, int n_in,
                              void *d_out, int out_size) {
  (void)in_sizes; (void)n_in; (void)out_size;
  const float *x  = (const float *)d_in[0];
  const float *W  = (const float *)d_in[1];
  const float *bx = (const float *)d_in[2];
  const float *bh = (const float *)d_in[3];

  static int attr_set = 0;
  if (!attr_set) {
    cudaFuncSetAttribute(gemm_h_kernel,
                         cudaFuncAttributeMaxDynamicSharedMemorySize, H_SMEM);
    cudaFuncSetAttribute(gemm_x_kernel,
                         cudaFuncAttributeMaxDynamicSharedMemorySize, X_SMEM);
    attr_set = 1;
  }

  zero_acc_kernel<<<1, 32>>>();
  conv_kernel<<<1024, 256>>>(x, bx);
  wsplit_kernel<<<2048, 256>>>(W);

  dim3 grdh(BB / 64, 1);
  dim3 grdx(BB / 64, DD / 64);

  for (int i = 0; i < 4; i++) {
    uint32_t h0, h1, xk0, xk1;
    tf2x32(0u, 42u, 0u, (uint32_t)(2 * i),     h0,  h1);
    tf2x32(0u, 42u, 0u, (uint32_t)(2 * i + 1), xk0, xk1);
    gemm_h_kernel<<<grdh, 256, H_SMEM>>>(bh, h0, h1, /*sample=*/1,
                                         /*slot=*/(i == 0) ? 0 : -1);
    gemm_x_kernel<<<grdx, 256, X_SMEM>>>(bx, xk0, xk1,
                                         /*bx_slot=*/(i == 3) ? 3 : -1);
  }
  // F(x_rec) softplus term
  gemm_h_kernel<<<grdh, 256, H_SMEM>>>(bh, 0u, 0u, /*sample=*/0, /*slot=*/1);

  finalize_kernel<<<1, 1>>>((float *)d_out);
}

// round 14
// speedup vs baseline: 1.3228x; 1.0024x over previous
#include <cuda_runtime.h>
#include <cuda_bf16.h>
#include <cstdint>
#include <math.h>

#define BB 16384
#define DD 4096
#define HH 128

// ---------------- scratch ----------------
__device__ __nv_bfloat16 g_xb[(size_t)BB * DD];     // visible sample (in-place chain)
__device__ __nv_bfloat16 g_hb[(size_t)BB * HH];     // hidden sample
__device__ __nv_bfloat16 g_Wx[2][(size_t)DD * HH];  // W splits, [d][h] (x-pass B)
__device__ __nv_bfloat16 g_Wh[2][(size_t)DD * HH];  // W splits, [h][d] (h-pass B)
__device__ double g_acc[4];

// ---------------- threefry2x32 (JAX-exact, verified R1-R13) ----------------
__host__ __device__ __forceinline__ uint32_t rotl32(uint32_t v, int s) {
  return (v << s) | (v >> (32 - s));
}
__host__ __device__ __forceinline__ void tf2x32(uint32_t k0, uint32_t k1,
                                                uint32_t x0, uint32_t x1,
                                                uint32_t &o0, uint32_t &o1) {
  uint32_t ks2 = k0 ^ k1 ^ 0x1BD11BDAu;
  x0 += k0; x1 += k1;
#define TF_R(r) { x0 += x1; x1 = rotl32(x1, r); x1 ^= x0; }
  TF_R(13) TF_R(15) TF_R(26) TF_R(6)   x0 += k1;  x1 += ks2 + 1u;
  TF_R(17) TF_R(29) TF_R(16) TF_R(24)  x0 += ks2; x1 += k0 + 2u;
  TF_R(13) TF_R(15) TF_R(26) TF_R(6)   x0 += k0;  x1 += k1 + 3u;
  TF_R(17) TF_R(29) TF_R(16) TF_R(24)  x0 += k1;  x1 += ks2 + 4u;
  TF_R(13) TF_R(15) TF_R(26) TF_R(6)   x0 += ks2; x1 += k0 + 5u;
#undef TF_R
  o0 = x0; o1 = x1;
}
__device__ __forceinline__ float jax_uniform01(uint32_t k0, uint32_t k1, uint32_t idx) {
  uint32_t a, b;
  tf2x32(k0, k1, 0u, idx, a, b);
  uint32_t bits = a ^ b;
  return __uint_as_float((bits >> 9) | 0x3F800000u) - 1.0f;
}
__device__ __forceinline__ float fast_sigmoid(float x) {
  float e, r;
  asm("ex2.approx.f32 %0, %1;" : "=f"(e) : "f"(-1.4426950408889634f * x));
  asm("rcp.approx.f32 %0, %1;" : "=f"(r) : "f"(1.0f + e));
  return r;
}
__device__ __forceinline__ float softplusf_(float x) {
  return fmaxf(x, 0.0f) + log1pf(expf(-fabsf(x)));
}

// ---------------- PTX helpers (baseline sm_100-safe) ----------------
__device__ __forceinline__ uint32_t smem_u32(const void *p) {
  uint32_t a;
  asm("{ .reg .u64 t; cvta.to.shared.u64 t, %1; cvt.u32.u64 %0, t; }"
      : "=r"(a) : "l"(p));
  return a;
}
__device__ __forceinline__ void ldsm4(uint32_t *r, uint32_t a) {
  asm volatile("ldmatrix.sync.aligned.m8n8.x4.shared.b16 {%0,%1,%2,%3}, [%4];"
               : "=r"(r[0]), "=r"(r[1]), "=r"(r[2]), "=r"(r[3]) : "r"(a));
}
__device__ __forceinline__ void mma_bf16(float *c, const uint32_t *a,
                                         uint32_t b0, uint32_t b1) {
  asm volatile(
      "mma.sync.aligned.m16n8k16.row.col.f32.bf16.bf16.f32 "
      "{%0,%1,%2,%3}, {%4,%5,%6,%7}, {%8,%9}, {%0,%1,%2,%3};"
      : "+f"(c[0]), "+f"(c[1]), "+f"(c[2]), "+f"(c[3])
      : "r"(a[0]), "r"(a[1]), "r"(a[2]), "r"(a[3]), "r"(b0), "r"(b1));
}
__device__ __forceinline__ uint32_t sw128(uint32_t o) {
  return o ^ ((o >> 3) & 0x70);
}

// load [ROWS x 64 bf16] tile, 128B rows, SW128-swizzled, via cp.async
template <int LD, int ROWS>
__device__ __forceinline__ void load_tile(uint32_t sdst, const __nv_bfloat16 *g,
                                          int row0, int kt) {
  int t = threadIdx.x;
#pragma unroll
  for (int i = 0; i < ROWS / 32; i++) {
    int idx = t + 256 * i;
    int r = idx >> 3, c = idx & 7;
    uint32_t sw = sw128((uint32_t)(r * 128 + c * 16));
    const void *ga = (const void *)(g + (size_t)(row0 + r) * LD + kt + c * 8);
    asm volatile("cp.async.cg.shared.global [%0], [%1], 16;"
                 :: "r"(sdst + sw), "l"(ga));
  }
}

// =============================================================
// h-pass (R5/R13 config): lin = x @ W + bh  M=16384 N=128 K=4096 (2 splits)
// CTA tile 64x128, BK=64, double-buffered; grid 256 -> 2 CTAs/SM.
// =============================================================
static constexpr int H_STAGE = 40960;
static constexpr int H_SMEM = 2 * H_STAGE;  // 81920

__global__ void __launch_bounds__(256, 2)
gemm_h_kernel(const float *__restrict__ bh_, uint32_t k0, uint32_t k1,
              int do_sample, int acc_slot) {
  extern __shared__ char smem[];
  uint32_t sb = smem_u32(smem);
  const int t = threadIdx.x, wid = t >> 5, l = t & 31;
  const int wm = wid & 1, wn = wid >> 1;
  const int m0 = blockIdx.x * 64;
  const int q = l >> 2, tq = l & 3;

  uint32_t offA[2], offB[2];
#pragma unroll
  for (int i = 0; i < 2; i++)
    offA[i] = (uint32_t)((wm * 32 + i * 16 + (l & 15)) * 128 + ((l >> 4) & 1) * 16);
#pragma unroll
  for (int jb = 0; jb < 2; jb++)
    offB[jb] = (uint32_t)((wn * 32 + jb * 16 + (l & 7) + ((l >> 4) & 1) * 8) * 128 +
                          ((l >> 3) & 1) * 16);

  float acc[2][4][4];
#pragma unroll
  for (int i = 0; i < 2; i++)
#pragma unroll
    for (int j = 0; j < 4; j++)
#pragma unroll
      for (int v = 0; v < 4; v++) acc[i][j][v] = 0.0f;

  auto issue_load = [&](int c) {
    int s = c & 1, kt = c * 64;
    uint32_t base = sb + s * H_STAGE;
    load_tile<DD, 64>(base, g_xb, m0, kt);
#pragma unroll
    for (int p = 0; p < 2; p++)
      load_tile<DD, 128>(base + 8192 + 16384 * p, g_Wh[p], 0, kt);
    asm volatile("cp.async.commit_group;" ::: "memory");
  };

  issue_load(0); issue_load(1);

#pragma unroll 1
  for (int c = 0; c < 64; c++) {
    if (c + 1 < 64) asm volatile("cp.async.wait_group 1;" ::: "memory");
    else            asm volatile("cp.async.wait_group 0;" ::: "memory");
    __syncthreads();
    uint32_t base = sb + (uint32_t)(c & 1) * H_STAGE;
#pragma unroll
    for (int kk = 0; kk < 4; kk++) {
      uint32_t a[2][4];
#pragma unroll
      for (int i = 0; i < 2; i++)
        ldsm4(a[i], base + sw128(offA[i] + kk * 32));
#pragma unroll
      for (int p = 0; p < 2; p++) {
        uint32_t bb = base + 8192u + 16384u * p;
#pragma unroll
        for (int jb = 0; jb < 2; jb++) {
          uint32_t b[4];
          ldsm4(b, bb + sw128(offB[jb] + kk * 32));
#pragma unroll
          for (int i = 0; i < 2; i++) {
            mma_bf16(acc[i][jb * 2 + 0], a[i], b[0], b[1]);
            mma_bf16(acc[i][jb * 2 + 1], a[i], b[2], b[3]);
          }
        }
      }
    }
    __syncthreads();
    if (c + 2 < 64) issue_load(c + 2);
  }

  // epilogue: bias + softplus and/or threefry sample into g_hb
  double sp = 0.0;
  const __nv_bfloat16 onev = __float2bfloat16(1.0f);
  const __nv_bfloat16 zerov = __float2bfloat16(0.0f);
#pragma unroll
  for (int i = 0; i < 2; i++) {
#pragma unroll
    for (int j = 0; j < 4; j++) {
      int col = wn * 32 + j * 8 + 2 * tq;
      float2 b2 = *(const float2 *)&bh_[col];
#pragma unroll
      for (int h = 0; h < 2; h++) {
        int gr = m0 + wm * 32 + i * 16 + q + h * 8;
        float l0 = acc[i][j][2 * h + 0] + b2.x;
        float l1 = acc[i][j][2 * h + 1] + b2.y;
        if (acc_slot >= 0)
          sp += (double)softplusf_(l0) + (double)softplusf_(l1);
        if (do_sample) {
          float p0 = fast_sigmoid(l0), p1 = fast_sigmoid(l1);
          uint32_t idx0 = (uint32_t)gr * (uint32_t)HH + (uint32_t)col;
          float u0 = jax_uniform01(k0, k1, idx0);
          float u1 = jax_uniform01(k0, k1, idx0 + 1u);
          __nv_bfloat162 v;
          v.x = (u0 < p0) ? onev : zerov;
          v.y = (u1 < p1) ? onev : zerov;
          *(__nv_bfloat162 *)&g_hb[(size_t)gr * HH + col] = v;
        }
      }
    }
  }
  if (acc_slot >= 0) {
#pragma unroll
    for (int o = 16; o > 0; o >>= 1) sp += __shfl_down_sync(0xffffffffu, sp, o);
    if (l == 0) atomicAdd(&g_acc[acc_slot], sp);
  }
}

// =============================================================
// x-pass: lin = h @ W^T + bx   M=16384 N=4096 K=128 (2 splits)
// CTA tile 64(M) x 64(N); 4 CTAs/SM (64-reg cap); all loads upfront.
// smem: A 2x8KB @0; B @16384 (2 chunks x 2 splits x 8KB = 32KB);
//       staging REUSES B chunk-0 region @16384 after compute (sync-guarded).
// =============================================================
static constexpr int X_STG_PITCH = 136;
static constexpr int X_SMEM = 49152;

__global__ void __launch_bounds__(256, 4)
gemm_x_kernel(const float *__restrict__ bx_, uint32_t k0, uint32_t k1,
              int bx_slot) {
  extern __shared__ char smem[];
  uint32_t sb = smem_u32(smem);
  const int t = threadIdx.x, wid = t >> 5, l = t & 31;
  const int wm = wid & 1, wn = wid >> 1;
  const int m0 = blockIdx.x * 64, n0 = blockIdx.y * 64;
  const int q = l >> 2, tq = l & 3;

  uint32_t offA[2], offB;
#pragma unroll
  for (int i = 0; i < 2; i++)
    offA[i] = (uint32_t)((wm * 32 + i * 16 + (l & 15)) * 128 + ((l >> 4) & 1) * 16);
  offB = (uint32_t)((wn * 16 + (l & 7) + ((l >> 4) & 1) * 8) * 128 +
                    ((l >> 3) & 1) * 16);

  // all loads upfront (K=128 -> 2 chunks)
#pragma unroll
  for (int kc = 0; kc < 2; kc++) {
    load_tile<HH, 64>(sb + kc * 8192, g_hb, m0, kc * 64);
#pragma unroll
    for (int p = 0; p < 2; p++)
      load_tile<HH, 64>(sb + 16384 + kc * 16384 + p * 8192, g_Wx[p], n0, kc * 64);
  }
  asm volatile("cp.async.commit_group;" ::: "memory");

  float acc[2][2][4];
#pragma unroll
  for (int i = 0; i < 2; i++)
#pragma unroll
    for (int j = 0; j < 2; j++)
#pragma unroll
      for (int v = 0; v < 4; v++) acc[i][j][v] = 0.0f;

  asm volatile("cp.async.wait_group 0;" ::: "memory");
  __syncthreads();

#pragma unroll
  for (int kc = 0; kc < 2; kc++) {
    uint32_t abase = sb + (uint32_t)kc * 8192;
    uint32_t bbase = sb + 16384u + (uint32_t)kc * 16384;
#pragma unroll
    for (int kk = 0; kk < 4; kk++) {
      uint32_t a[2][4];
#pragma unroll
      for (int i = 0; i < 2; i++)
        ldsm4(a[i], abase + sw128(offA[i] + kk * 32));
#pragma unroll
      for (int p = 0; p < 2; p++) {
        uint32_t b[4];
        ldsm4(b, bbase + p * 8192u + sw128(offB + kk * 32));
#pragma unroll
        for (int i = 0; i < 2; i++) {
          mma_bf16(acc[i][0], a[i], b[0], b[1]);
          mma_bf16(acc[i][1], a[i], b[2], b[3]);
        }
      }
    }
  }
  __syncthreads();  // all warps done reading B before staging overwrites it

  // epilogue: bias + threefry sample -> staging (B region) -> coalesced store
  double spb = 0.0;
  const __nv_bfloat16 onev = __float2bfloat16(1.0f);
  const __nv_bfloat16 zerov = __float2bfloat16(0.0f);
  char *stg = smem + 16384;
#pragma unroll
  for (int j = 0; j < 2; j++) {
    int col = wn * 16 + j * 8 + 2 * tq;
    float2 b2 = *(const float2 *)&bx_[n0 + col];
#pragma unroll
    for (int i = 0; i < 2; i++) {
#pragma unroll
      for (int h = 0; h < 2; h++) {
        int row = wm * 32 + i * 16 + q + h * 8;
        float l0 = acc[i][j][2 * h + 0] + b2.x;
        float l1 = acc[i][j][2 * h + 1] + b2.y;
        float p0 = fast_sigmoid(l0), p1 = fast_sigmoid(l1);
        uint32_t idx0 = (uint32_t)(m0 + row) * (uint32_t)DD + (uint32_t)(n0 + col);
        float u0 = jax_uniform01(k0, k1, idx0);
        float u1 = jax_uniform01(k0, k1, idx0 + 1u);
        bool s0 = (u0 < p0), s1 = (u1 < p1);
        if (bx_slot >= 0) {
          if (s0) spb += (double)b2.x;
          if (s1) spb += (double)b2.y;
        }
        __nv_bfloat162 v;
        v.x = s0 ? onev : zerov;
        v.y = s1 ? onev : zerov;
        *(__nv_bfloat162 *)(stg + row * X_STG_PITCH + col * 2) = v;
      }
    }
  }
  if (bx_slot >= 0) {
#pragma unroll
    for (int o = 16; o > 0; o >>= 1) spb += __shfl_down_sync(0xffffffffu, spb, o);
    if (l == 0) atomicAdd(&g_acc[bx_slot], spb);
  }
  __syncthreads();
#pragma unroll
  for (int i2 = 0; i2 < 4; i2++) {
    int idx = t + 256 * i2;
    int rr = idx >> 4, c8 = idx & 15;
    uint64_t v = *(const uint64_t *)(stg + rr * X_STG_PITCH + c8 * 8);
    *(uint64_t *)&g_xb[(size_t)(m0 + rr) * DD + n0 + c8 * 4] = v;
  }
}

// ---------------- prep: conv (+x.bx) and wsplit merged ----------------
__global__ void prep_kernel(const float *__restrict__ x,
                            const float *__restrict__ bx,
                            const float *__restrict__ W) {
  if (blockIdx.x < 1024) {
    size_t n = (size_t)BB * DD / 4;
    double s = 0.0;
    for (size_t i = (size_t)blockIdx.x * blockDim.x + threadIdx.x; i < n;
         i += (size_t)1024 * blockDim.x) {
      float4 v = ((const float4 *)x)[i];
      ushort4 o;
      o.x = __bfloat16_as_ushort(__float2bfloat16(v.x));
      o.y = __bfloat16_as_ushort(__float2bfloat16(v.y));
      o.z = __bfloat16_as_ushort(__float2bfloat16(v.z));
      o.w = __bfloat16_as_ushort(__float2bfloat16(v.w));
      ((ushort4 *)g_xb)[i] = o;
      uint32_t d = (uint32_t)((i * 4) & (DD - 1));
      const float4 b4 = *(const float4 *)&bx[d];
      s += (double)(v.x * b4.x + v.y * b4.y) + (double)(v.z * b4.z + v.w * b4.w);
    }
#pragma unroll
    for (int off = 16; off > 0; off >>= 1)
      s += __shfl_down_sync(0xffffffffu, s, off);
    if ((threadIdx.x & 31) == 0) atomicAdd(&g_acc[2], s);
  } else {
    int n = DD * HH;
    for (int i = (blockIdx.x - 1024) * blockDim.x + threadIdx.x; i < n;
         i += 256 * blockDim.x) {
      float w = W[i];
      __nv_bfloat16 b0 = __float2bfloat16(w);
      float r1 = w - __bfloat162float(b0);
      __nv_bfloat16 b1 = __float2bfloat16(r1);
      g_Wx[0][i] = b0; g_Wx[1][i] = b1;
      int d = i >> 7, h = i & 127;
      int j = h * DD + d;
      g_Wh[0][j] = b0; g_Wh[1][j] = b1;
    }
  }
}

__global__ void zero_acc_kernel() {
  if (threadIdx.x < 4) g_acc[threadIdx.x] = 0.0;
}

// cd = meanF(x) - meanF(x_rec); F = -sum softplus - v.bx
__global__ void finalize_kernel(float *out) {
  double cd = (-g_acc[0] - g_acc[2] + g_acc[1] + g_acc[3]) / (double)BB;
  out[0] = (float)cd;
}

// =============================================================
extern "C" void kernel_launch(void *const *d_in, const int *in_sizes, int n_in,
                              void *d_out, int out_size) {
  (void)in_sizes; (void)n_in; (void)out_size;
  const float *x  = (const float *)d_in[0];
  const float *W  = (const float *)d_in[1];
  const float *bx = (const float *)d_in[2];
  const float *bh = (const float *)d_in[3];

  static int attr_set = 0;
  if (!attr_set) {
    cudaFuncSetAttribute(gemm_h_kernel,
                         cudaFuncAttributeMaxDynamicSharedMemorySize, H_SMEM);
    cudaFuncSetAttribute(gemm_x_kernel,
                         cudaFuncAttributeMaxDynamicSharedMemorySize, X_SMEM);
    attr_set = 1;
  }

  zero_acc_kernel<<<1, 32>>>();
  prep_kernel<<<1280, 256>>>(x, bx, W);

  dim3 grdh(BB / 64, 1);
  dim3 grdx(BB / 64, DD / 64);

  for (int i = 0; i < 4; i++) {
    uint32_t h0, h1, xk0, xk1;
    tf2x32(0u, 42u, 0u, (uint32_t)(2 * i),     h0,  h1);
    tf2x32(0u, 42u, 0u, (uint32_t)(2 * i + 1), xk0, xk1);
    gemm_h_kernel<<<grdh, 256, H_SMEM>>>(bh, h0, h1, /*sample=*/1,
                                         /*slot=*/(i == 0) ? 0 : -1);
    gemm_x_kernel<<<grdx, 256, X_SMEM>>>(bx, xk0, xk1,
                                         /*bx_slot=*/(i == 3) ? 3 : -1);
  }
  // F(x_rec) softplus term
  gemm_h_kernel<<<grdh, 256, H_SMEM>>>(bh, 0u, 0u, /*sample=*/0, /*slot=*/1);

  finalize_kernel<<<1, 1>>>((float *)d_out);
}